// round 13
// baseline (speedup 1.0000x reference)
#include <cuda_runtime.h>
#include <cuda_fp16.h>
#include <cstdint>
#include <math.h>

#define B 32
#define T 2048
#define H 1024
#define NEGV (-1e9f)

// ---------------------------------------------------------------------------
// Device scratch
// ---------------------------------------------------------------------------
__device__ __align__(256) __half g_enc_h[B * T * H];   // fp16(enc), unmasked rows only
__device__ __align__(256) __half g_W_h[H * H];         // fp16(32*W_enc)
__device__ float g_dec_p[B * H];
__device__ float g_scores[B * T];
__device__ int   g_cidx[B * T];                        // compacted t-indices per batch
__device__ int   g_cnt[B];
__device__ int   g_done[B];                            // scores-block completion counters

// ---------------------------------------------------------------------------
// helpers
// ---------------------------------------------------------------------------
__device__ __forceinline__ uint32_t smem_u32(const void* p) {
    uint32_t a;
    asm("{ .reg .u64 t; cvta.to.shared.u64 t, %1; cvt.u32.u64 %0, t; }" : "=r"(a) : "l"(p));
    return a;
}
#define CP_ASYNC_16(dst, src) \
    asm volatile("cp.async.cg.shared.global [%0], [%1], 16;" :: "r"(dst), "l"(src) : "memory")
#define CP_COMMIT() asm volatile("cp.async.commit_group;" ::: "memory")
#define CP_WAIT1()  asm volatile("cp.async.wait_group 1;" ::: "memory")

#define LDSM_X4(r0, r1, r2, r3, addr) \
    asm volatile("ldmatrix.sync.aligned.m8n8.x4.shared.b16 {%0,%1,%2,%3}, [%4];" \
        : "=r"(r0), "=r"(r1), "=r"(r2), "=r"(r3) : "r"(addr))

#define MMA16816(c0, c1, c2, c3, a0, a1, a2, a3, b0, b1) \
    asm volatile("mma.sync.aligned.m16n8k16.row.col.f32.f16.f16.f32 " \
        "{%0,%1,%2,%3}, {%4,%5,%6,%7}, {%8,%9}, {%0,%1,%2,%3};" \
        : "+f"(c0), "+f"(c1), "+f"(c2), "+f"(c3) \
        : "r"(a0), "r"(a1), "r"(a2), "r"(a3), "r"(b0), "r"(b1))

// fast tanh: 2 MUFU + FMAs, abs err ~1e-6
__device__ __forceinline__ float fast_tanh(float x) {
    float e;
    asm("ex2.approx.f32 %0, %1;" : "=f"(e) : "f"(x * 2.8853900817779268f));
    float r;
    asm("rcp.approx.f32 %0, %1;" : "=f"(r) : "f"(e + 1.0f));
    return fmaf(-2.0f, r, 1.0f);
}

// ---------------------------------------------------------------------------
// Compaction + per-replay state reset (dec_p zero, done counters)
// ---------------------------------------------------------------------------
__global__ void compact_kernel(const int* __restrict__ mask) {
    __shared__ int warp_cnt[8];
    __shared__ int base;
    const int b = blockIdx.x;
    const int tid = threadIdx.x;
    const int lane = tid & 31, w = tid >> 5;
    // reset per-replay state
#pragma unroll
    for (int i = 0; i < 4; i++) g_dec_p[b * H + i * 256 + tid] = 0.f;
    if (tid == 0) {
        g_done[b] = 0;
        base = 0;
    }
    __syncthreads();
    for (int t0 = 0; t0 < T; t0 += 256) {
        const int cur = base;
        const int t = t0 + tid;
        const int m = (mask[b * T + t] != 0);
        unsigned bal = __ballot_sync(0xffffffffu, m);
        int pre = __popc(bal & ((1u << lane) - 1u));
        if (lane == 0) warp_cnt[w] = __popc(bal);
        __syncthreads();
        int woff = 0, tot = 0;
#pragma unroll
        for (int i = 0; i < 8; i++) {
            if (i < w) woff += warp_cnt[i];
            tot += warp_cnt[i];
        }
        if (m) g_cidx[b * T + cur + woff + pre] = t;
        __syncthreads();
        if (tid == 0) base = cur + tot;
        __syncthreads();
    }
    if (tid == 0) g_cnt[b] = base;
}

// ---------------------------------------------------------------------------
// Conversion kernels (enc: only unmasked rows)
// ---------------------------------------------------------------------------
__global__ void conv_enc_kernel(const float* __restrict__ src,
                                const int* __restrict__ mask) {
    int i = (blockIdx.x * blockDim.x + threadIdx.x) * 4;
    if (i >= B * T * H) return;
    if (mask[i >> 10] == 0) return;   // row = i / H indexes [B,T] directly
    float4 x = *(const float4*)(src + i);
    __half2 p0, p1;
    p0.x = __float2half(x.x); p0.y = __float2half(x.y);
    p1.x = __float2half(x.z); p1.y = __float2half(x.w);
    *(__half2*)(g_enc_h + i) = p0;
    *(__half2*)(g_enc_h + i + 2) = p1;
}

__global__ void conv_W_kernel(const float* __restrict__ src) {
    int i = (blockIdx.x * blockDim.x + threadIdx.x) * 4;
    if (i >= H * H) return;
    float4 x = *(const float4*)(src + i);
    __half2 p0, p1;
    p0.x = __float2half(x.x * 32.f); p0.y = __float2half(x.y * 32.f);
    p1.x = __float2half(x.z * 32.f); p1.y = __float2half(x.w * 32.f);
    *(__half2*)(g_W_h + i) = p0;
    *(__half2*)(g_W_h + i + 2) = p1;
}

// ---------------------------------------------------------------------------
// Split-K dec_proj mini-GEMM: grid (32 o-tiles, 8 k-chunks), atomicAdd.
// ---------------------------------------------------------------------------
__global__ __launch_bounds__(256, 2) void dec_proj_kernel(const float* __restrict__ dec,
                                                          const float* __restrict__ Wd) {
    __shared__ float sd[32][132];
    __shared__ float sw[32][132];
    const int o0 = blockIdx.x * 32;
    const int h0 = blockIdx.y * 128;
    const int tid = threadIdx.x;
    const int tx = tid & 15, ty = tid >> 4;
    float c00 = 0.f, c01 = 0.f, c10 = 0.f, c11 = 0.f;

#pragma unroll
    for (int i = 0; i < 4; i++) {
        int idx = i * 256 + tid;
        int row = idx >> 5;
        int col = (idx & 31) * 4;
        float4 xv = *(const float4*)(dec + (size_t)row * H + h0 + col);
        sd[row][col + 0] = xv.x; sd[row][col + 1] = xv.y;
        sd[row][col + 2] = xv.z; sd[row][col + 3] = xv.w;
        float4 wv = *(const float4*)(Wd + (size_t)(o0 + row) * H + h0 + col);
        sw[row][col + 0] = wv.x; sw[row][col + 1] = wv.y;
        sw[row][col + 2] = wv.z; sw[row][col + 3] = wv.w;
    }
    __syncthreads();
#pragma unroll 8
    for (int h = 0; h < 128; h++) {
        float a0 = sd[ty * 2][h], a1 = sd[ty * 2 + 1][h];
        float w0 = sw[tx * 2][h], w1 = sw[tx * 2 + 1][h];
        c00 = fmaf(a0, w0, c00); c01 = fmaf(a0, w1, c01);
        c10 = fmaf(a1, w0, c10); c11 = fmaf(a1, w1, c11);
    }
    const int b0 = ty * 2, oo = o0 + tx * 2;
    atomicAdd(&g_dec_p[b0 * H + oo], c00);
    atomicAdd(&g_dec_p[b0 * H + oo + 1], c01);
    atomicAdd(&g_dec_p[(b0 + 1) * H + oo], c10);
    atomicAdd(&g_dec_p[(b0 + 1) * H + oo + 1], c11);
}

// ---------------------------------------------------------------------------
// Fused HMMA scores kernel on COMPACTED rows + fused tail softmax.
//   Block tile 128(Mc) x 128(N-chunk), K = 1024, k-tile 64, 3-stage cp.async,
//   256 threads / 8 warps (4x2), warp tile 32x64, 2 CTAs/SM.
//   Last finishing block per batch performs the masked softmax inline.
// ---------------------------------------------------------------------------
#define NCH 8
#define KT_PER_CH 16       // 1024 / 64
#define NJOBS (NCH * KT_PER_CH)   // 128
#define A_STAGE 16384
#define STAGE 32768
#define VDP_OFF 98304
#define SROW_OFF 106496
#define RIDX_OFF 107008
#define SMEM_TOTAL 107520

__device__ __forceinline__ void load_job(uint32_t sb, const int* __restrict__ ridx,
                                         int slot, int j, int bT) {
    const int c = j >> 4, kt = j & 15;
    const int ksrc = kt << 6;
    const uint32_t aB = sb + slot * STAGE;
    const uint32_t bB = aB + A_STAGE;
    const int tid = threadIdx.x;
    const int n0 = c << 7;
#pragma unroll
    for (int i = 0; i < 4; i++) {         // A: 128 gathered rows x 128B
        int ch = i * 256 + tid;
        int row = ch >> 3, cu = ch & 7;
        uint32_t dst = aB + row * 128 + ((cu ^ (row & 7)) << 4);
        CP_ASYNC_16(dst, g_enc_h + (size_t)(bT + ridx[row]) * H + ksrc + cu * 8);
    }
#pragma unroll
    for (int i = 0; i < 4; i++) {         // B: 128 rows x 128B
        int ch = i * 256 + tid;
        int row = ch >> 3, cu = ch & 7;
        uint32_t dst = bB + row * 128 + ((cu ^ (row & 7)) << 4);
        CP_ASYNC_16(dst, g_W_h + (size_t)(n0 + row) * H + ksrc + cu * 8);
    }
}

__global__ __launch_bounds__(256, 2) void scores_tc_kernel(const float* __restrict__ v_g,
                                                           const int* __restrict__ mask,
                                                           float* __restrict__ attn) {
    extern __shared__ char sm[];
    __shared__ float sred[8];
    __shared__ int s_last;
    const uint32_t sb = smem_u32(sm);
    const int tid = threadIdx.x;
    const int b = blockIdx.x >> 4;
    const int m0 = (blockIdx.x & 15) * 128;
    const int cnt = g_cnt[b];
    if (m0 >= cnt) return;
    const int wid = tid >> 5, lane = tid & 31;
    const int wm = wid >> 1, wn = wid & 1;
    const int bT = b * T;

    float2* vdp = (float2*)(sm + VDP_OFF);
    float* srow = (float*)(sm + SROW_OFF);
    int* ridx = (int*)(sm + RIDX_OFF);
    for (int n = tid; n < H; n += 256) {
        float2 t;
        t.x = g_dec_p[b * H + n];
        t.y = v_g[n];
        vdp[n] = t;
    }
    if (tid < 128) {
        srow[tid] = 0.f;
        int j = m0 + tid;
        ridx[tid] = g_cidx[bT + (j < cnt ? j : cnt - 1)];
    }

    // ldmatrix per-lane geometry (warp tile 32M x 64N)
    int rA128[2], rAx[2], rB128[4], rBx[4];
#pragma unroll
    for (int mt = 0; mt < 2; mt++) {
        int row = wm * 32 + mt * 16 + ((lane >> 3) & 1) * 8 + (lane & 7);
        rA128[mt] = row * 128;
        rAx[mt] = row & 7;
    }
#pragma unroll
    for (int np = 0; np < 4; np++) {
        int row = wn * 64 + np * 16 + ((lane >> 4) << 3) + (lane & 7);
        rB128[np] = row * 128;
        rBx[np] = row & 7;
    }
    const int aU = lane >> 4;
    const int bU = (lane >> 3) & 1;

    __syncthreads();

    load_job(sb, ridx, 0, 0, bT); CP_COMMIT();
    load_job(sb, ridx, 1, 1, bT); CP_COMMIT();

    float c[2][8][4];
    float accA[2] = {0.f, 0.f};
    float accB[2] = {0.f, 0.f};
    int cch = 0, kt = 0;
    int slot = 0, slot2 = 2;

#pragma unroll 1
    for (int j = 0; j < NJOBS; j++) {
        CP_WAIT1();
        __syncthreads();
        {
            const int jn = j + 2;
            if (jn < NJOBS) load_job(sb, ridx, slot2, jn, bT);
            CP_COMMIT();
        }

        if (kt == 0) {
#pragma unroll
            for (int mt = 0; mt < 2; mt++)
#pragma unroll
                for (int nt = 0; nt < 8; nt++)
#pragma unroll
                    for (int q = 0; q < 4; q++) c[mt][nt][q] = 0.f;
        }

        const uint32_t aBase = sb + slot * STAGE;
        const uint32_t bBase = aBase + A_STAGE;

#pragma unroll
        for (int ks = 0; ks < 4; ks++) {
            uint32_t a[2][4];
#pragma unroll
            for (int mt = 0; mt < 2; mt++) {
                uint32_t ad = aBase + rA128[mt] + ((((ks << 1) + aU) ^ rAx[mt]) << 4);
                LDSM_X4(a[mt][0], a[mt][1], a[mt][2], a[mt][3], ad);
            }
            uint32_t bb[4][4];
#pragma unroll
            for (int np = 0; np < 4; np++) {
                uint32_t bd = bBase + rB128[np] + ((((ks << 1) + bU) ^ rBx[np]) << 4);
                LDSM_X4(bb[np][0], bb[np][1], bb[np][2], bb[np][3], bd);
            }
#pragma unroll
            for (int mt = 0; mt < 2; mt++)
#pragma unroll
                for (int np = 0; np < 4; np++) {
                    MMA16816(c[mt][2 * np][0], c[mt][2 * np][1], c[mt][2 * np][2], c[mt][2 * np][3],
                             a[mt][0], a[mt][1], a[mt][2], a[mt][3], bb[np][0], bb[np][1]);
                    MMA16816(c[mt][2 * np + 1][0], c[mt][2 * np + 1][1], c[mt][2 * np + 1][2], c[mt][2 * np + 1][3],
                             a[mt][0], a[mt][1], a[mt][2], a[mt][3], bb[np][2], bb[np][3]);
                }
        }

        if (kt == KT_PER_CH - 1) {
            const int nb = cch * 128 + wn * 64 + (lane & 3) * 2;
            const float inv32 = 0.03125f;
#pragma unroll
            for (int mt = 0; mt < 2; mt++)
#pragma unroll
                for (int nt = 0; nt < 8; nt++) {
                    int n = nb + nt * 8;
                    float2 d0 = vdp[n], d1 = vdp[n + 1];
                    accA[mt] += d0.y * fast_tanh(fmaf(c[mt][nt][0], inv32, d0.x))
                              + d1.y * fast_tanh(fmaf(c[mt][nt][1], inv32, d1.x));
                    accB[mt] += d0.y * fast_tanh(fmaf(c[mt][nt][2], inv32, d0.x))
                              + d1.y * fast_tanh(fmaf(c[mt][nt][3], inv32, d1.x));
                }
            cch++;
            kt = 0;
        } else {
            kt++;
        }
        slot = (slot == 2) ? 0 : slot + 1;
        slot2 = (slot2 == 2) ? 0 : slot2 + 1;
    }

    // reduce and write scores for this block's rows
#pragma unroll
    for (int mt = 0; mt < 2; mt++) {
        accA[mt] += __shfl_xor_sync(0xffffffffu, accA[mt], 1);
        accA[mt] += __shfl_xor_sync(0xffffffffu, accA[mt], 2);
        accB[mt] += __shfl_xor_sync(0xffffffffu, accB[mt], 1);
        accB[mt] += __shfl_xor_sync(0xffffffffu, accB[mt], 2);
        if ((lane & 3) == 0) {
            int r = wm * 32 + mt * 16 + (lane >> 2);
            atomicAdd(&srow[r], accA[mt]);
            atomicAdd(&srow[r + 8], accB[mt]);
        }
    }
    __syncthreads();
    if (tid < 128 && m0 + tid < cnt) g_scores[bT + ridx[tid]] = srow[tid];

    // ---- fused tail softmax: last finishing block of this batch ----
    const int nblk = (cnt + 127) >> 7;
    if (tid == 0) {
        __threadfence();
        int prev = atomicAdd(&g_done[b], 1);
        s_last = (prev == nblk - 1);
    }
    __syncthreads();
    if (!s_last) return;

    float vals[8];
    float mx = -INFINITY;
#pragma unroll
    for (int i = 0; i < 8; i++) {
        int t = tid + i * 256;
        float sc = (mask[bT + t] == 0) ? NEGV : g_scores[bT + t];
        vals[i] = sc;
        mx = fmaxf(mx, sc);
    }
#pragma unroll
    for (int off = 16; off; off >>= 1)
        mx = fmaxf(mx, __shfl_xor_sync(0xffffffffu, mx, off));
    if ((tid & 31) == 0) sred[tid >> 5] = mx;
    __syncthreads();
    if (tid < 32) {
        float m = (tid < 8) ? sred[tid] : -INFINITY;
#pragma unroll
        for (int off = 4; off; off >>= 1)
            m = fmaxf(m, __shfl_xor_sync(0xffffffffu, m, off));
        if (tid == 0) sred[0] = m;
    }
    __syncthreads();
    mx = sred[0];

    float sum = 0.f;
#pragma unroll
    for (int i = 0; i < 8; i++) {
        vals[i] = expf(vals[i] - mx);
        sum += vals[i];
    }
#pragma unroll
    for (int off = 16; off; off >>= 1)
        sum += __shfl_xor_sync(0xffffffffu, sum, off);
    __syncthreads();
    if ((tid & 31) == 0) sred[tid >> 5] = sum;
    __syncthreads();
    if (tid < 32) {
        float s = (tid < 8) ? sred[tid] : 0.f;
#pragma unroll
        for (int off = 4; off; off >>= 1)
            s += __shfl_xor_sync(0xffffffffu, s, off);
        if (tid == 0) sred[0] = s;
    }
    __syncthreads();
    const float inv = 1.f / sred[0];
#pragma unroll
    for (int i = 0; i < 8; i++)
        attn[bT + tid + i * 256] = vals[i] * inv;
}

// ---------------------------------------------------------------------------
// context[b,h] = sum over UNMASKED t of attn[b,t]*enc_h[b,t,h]  (fp16 enc)
// ---------------------------------------------------------------------------
#define TSPLIT 8
__global__ void context_kernel(const float* __restrict__ attn,
                               float* __restrict__ ctx) {
    __shared__ float w[256];
    __shared__ int ti[256];
    const int b = blockIdx.y;
    const int cnt = g_cnt[b];
    const int chunk = (cnt + TSPLIT - 1) / TSPLIT;
    const int j0 = blockIdx.z * chunk;
    const int len = min(chunk, cnt - j0);
    const int tid = threadIdx.x;
    for (int j = tid; j < len; j += 256) {
        int t = g_cidx[b * T + j0 + j];
        ti[j] = t;
        w[j] = attn[b * T + t];
    }
    __syncthreads();
    if (len <= 0) return;

    const int h = blockIdx.x * 512 + tid * 2;
    const __half* e = g_enc_h + (size_t)b * T * H + h;
    float a0 = 0.f, a1 = 0.f;
#pragma unroll 4
    for (int j = 0; j < len; j++) {
        __half2 v2 = *(const __half2*)(e + (size_t)ti[j] * H);
        float2 f2 = __half22float2(v2);
        a0 = fmaf(w[j], f2.x, a0);
        a1 = fmaf(w[j], f2.y, a1);
    }
    atomicAdd(&ctx[b * H + h], a0);
    atomicAdd(&ctx[b * H + h + 1], a1);
}

// ---------------------------------------------------------------------------
extern "C" void kernel_launch(void* const* d_in, const int* in_sizes, int n_in,
                              void* d_out, int out_size) {
    const float* dec  = (const float*)d_in[0];  // [B,H]
    const float* enc  = (const float*)d_in[1];  // [B,T,H]
    const int*   mask = (const int*)d_in[2];    // [B,T]
    const float* We   = (const float*)d_in[3];  // [H,H]
    const float* Wd   = (const float*)d_in[4];  // [H,H]
    const float* v    = (const float*)d_in[5];  // [H]

    float* ctx  = (float*)d_out;                // [B,H]
    float* attn = (float*)d_out + B * H;        // [B,T]

    cudaFuncSetAttribute(scores_tc_kernel,
                         cudaFuncAttributeMaxDynamicSharedMemorySize, SMEM_TOTAL);

    compact_kernel<<<B, 256>>>(mask);
    conv_enc_kernel<<<(B * T * H / 4 + 255) / 256, 256>>>(enc, mask);
    conv_W_kernel<<<(H * H / 4 + 255) / 256, 256>>>(We);
    dec_proj_kernel<<<dim3(H / 32, 8), 256>>>(dec, Wd);
    cudaMemsetAsync(ctx, 0, (size_t)B * H * sizeof(float));

    scores_tc_kernel<<<B * 16, 256, SMEM_TOTAL>>>(v, mask, attn);

    context_kernel<<<dim3(H / 512, B, TSPLIT), 256>>>(attn, ctx);
}

// round 14
// speedup vs baseline: 1.1932x; 1.1932x over previous
#include <cuda_runtime.h>
#include <cuda_fp16.h>
#include <cstdint>
#include <math.h>

#define B 32
#define T 2048
#define H 1024
#define NEGV (-1e9f)

// ---------------------------------------------------------------------------
// Device scratch
// ---------------------------------------------------------------------------
__device__ __align__(256) __half g_enc_h[B * T * H];   // fp16(enc), unmasked rows only
__device__ __align__(256) __half g_W_h[H * H];         // fp16(32*W_enc)
__device__ float g_dec_p[B * H];
__device__ float g_scores[B * T];
__device__ int   g_cidx[B * T];                        // compacted t-indices per batch
__device__ int   g_cnt[B];

// ---------------------------------------------------------------------------
// helpers
// ---------------------------------------------------------------------------
__device__ __forceinline__ uint32_t smem_u32(const void* p) {
    uint32_t a;
    asm("{ .reg .u64 t; cvta.to.shared.u64 t, %1; cvt.u32.u64 %0, t; }" : "=r"(a) : "l"(p));
    return a;
}
#define CP_ASYNC_16(dst, src) \
    asm volatile("cp.async.cg.shared.global [%0], [%1], 16;" :: "r"(dst), "l"(src) : "memory")
#define CP_COMMIT() asm volatile("cp.async.commit_group;" ::: "memory")
#define CP_WAIT1()  asm volatile("cp.async.wait_group 1;" ::: "memory")

#define LDSM_X4(r0, r1, r2, r3, addr) \
    asm volatile("ldmatrix.sync.aligned.m8n8.x4.shared.b16 {%0,%1,%2,%3}, [%4];" \
        : "=r"(r0), "=r"(r1), "=r"(r2), "=r"(r3) : "r"(addr))

#define MMA16816(c0, c1, c2, c3, a0, a1, a2, a3, b0, b1) \
    asm volatile("mma.sync.aligned.m16n8k16.row.col.f32.f16.f16.f32 " \
        "{%0,%1,%2,%3}, {%4,%5,%6,%7}, {%8,%9}, {%0,%1,%2,%3};" \
        : "+f"(c0), "+f"(c1), "+f"(c2), "+f"(c3) \
        : "r"(a0), "r"(a1), "r"(a2), "r"(a3), "r"(b0), "r"(b1))

// fast tanh: 2 MUFU + FMAs, abs err ~1e-6
__device__ __forceinline__ float fast_tanh(float x) {
    float e;
    asm("ex2.approx.f32 %0, %1;" : "=f"(e) : "f"(x * 2.8853900817779268f));
    float r;
    asm("rcp.approx.f32 %0, %1;" : "=f"(r) : "f"(e + 1.0f));
    return fmaf(-2.0f, r, 1.0f);
}

// ---------------------------------------------------------------------------
// Compaction + dec_p zeroing (per-replay state reset)
// ---------------------------------------------------------------------------
__global__ void compact_kernel(const int* __restrict__ mask) {
    __shared__ int warp_cnt[8];
    __shared__ int base;
    const int b = blockIdx.x;
    const int tid = threadIdx.x;
    const int lane = tid & 31, w = tid >> 5;
#pragma unroll
    for (int i = 0; i < 4; i++) g_dec_p[b * H + i * 256 + tid] = 0.f;
    if (tid == 0) base = 0;
    __syncthreads();
    for (int t0 = 0; t0 < T; t0 += 256) {
        const int cur = base;
        const int t = t0 + tid;
        const int m = (mask[b * T + t] != 0);
        unsigned bal = __ballot_sync(0xffffffffu, m);
        int pre = __popc(bal & ((1u << lane) - 1u));
        if (lane == 0) warp_cnt[w] = __popc(bal);
        __syncthreads();
        int woff = 0, tot = 0;
#pragma unroll
        for (int i = 0; i < 8; i++) {
            if (i < w) woff += warp_cnt[i];
            tot += warp_cnt[i];
        }
        if (m) g_cidx[b * T + cur + woff + pre] = t;
        __syncthreads();
        if (tid == 0) base = cur + tot;
        __syncthreads();
    }
    if (tid == 0) g_cnt[b] = base;
}

// ---------------------------------------------------------------------------
// Conversion kernels (enc: only unmasked rows)
// ---------------------------------------------------------------------------
__global__ void conv_enc_kernel(const float* __restrict__ src,
                                const int* __restrict__ mask) {
    int i = (blockIdx.x * blockDim.x + threadIdx.x) * 4;
    if (i >= B * T * H) return;
    if (mask[i >> 10] == 0) return;   // row = i / H indexes [B,T] directly
    float4 x = *(const float4*)(src + i);
    __half2 p0, p1;
    p0.x = __float2half(x.x); p0.y = __float2half(x.y);
    p1.x = __float2half(x.z); p1.y = __float2half(x.w);
    *(__half2*)(g_enc_h + i) = p0;
    *(__half2*)(g_enc_h + i + 2) = p1;
}

__global__ void conv_W_kernel(const float* __restrict__ src) {
    int i = (blockIdx.x * blockDim.x + threadIdx.x) * 4;
    if (i >= H * H) return;
    float4 x = *(const float4*)(src + i);
    __half2 p0, p1;
    p0.x = __float2half(x.x * 32.f); p0.y = __float2half(x.y * 32.f);
    p1.x = __float2half(x.z * 32.f); p1.y = __float2half(x.w * 32.f);
    *(__half2*)(g_W_h + i) = p0;
    *(__half2*)(g_W_h + i + 2) = p1;
}

// ---------------------------------------------------------------------------
// Split-K dec_proj mini-GEMM: grid (32 o-tiles, 8 k-chunks), atomicAdd.
// ---------------------------------------------------------------------------
__global__ __launch_bounds__(256, 2) void dec_proj_kernel(const float* __restrict__ dec,
                                                          const float* __restrict__ Wd) {
    __shared__ float sd[32][132];
    __shared__ float sw[32][132];
    const int o0 = blockIdx.x * 32;
    const int h0 = blockIdx.y * 128;
    const int tid = threadIdx.x;
    const int tx = tid & 15, ty = tid >> 4;
    float c00 = 0.f, c01 = 0.f, c10 = 0.f, c11 = 0.f;

#pragma unroll
    for (int i = 0; i < 4; i++) {
        int idx = i * 256 + tid;
        int row = idx >> 5;
        int col = (idx & 31) * 4;
        float4 xv = *(const float4*)(dec + (size_t)row * H + h0 + col);
        sd[row][col + 0] = xv.x; sd[row][col + 1] = xv.y;
        sd[row][col + 2] = xv.z; sd[row][col + 3] = xv.w;
        float4 wv = *(const float4*)(Wd + (size_t)(o0 + row) * H + h0 + col);
        sw[row][col + 0] = wv.x; sw[row][col + 1] = wv.y;
        sw[row][col + 2] = wv.z; sw[row][col + 3] = wv.w;
    }
    __syncthreads();
#pragma unroll 8
    for (int h = 0; h < 128; h++) {
        float a0 = sd[ty * 2][h], a1 = sd[ty * 2 + 1][h];
        float w0 = sw[tx * 2][h], w1 = sw[tx * 2 + 1][h];
        c00 = fmaf(a0, w0, c00); c01 = fmaf(a0, w1, c01);
        c10 = fmaf(a1, w0, c10); c11 = fmaf(a1, w1, c11);
    }
    const int b0 = ty * 2, oo = o0 + tx * 2;
    atomicAdd(&g_dec_p[b0 * H + oo], c00);
    atomicAdd(&g_dec_p[b0 * H + oo + 1], c01);
    atomicAdd(&g_dec_p[(b0 + 1) * H + oo], c10);
    atomicAdd(&g_dec_p[(b0 + 1) * H + oo + 1], c11);
}

// ---------------------------------------------------------------------------
// Fused HMMA scores kernel on COMPACTED rows (R11-proven version)
//   Block tile 128(Mc) x 128(N-chunk), K = 1024, k-tile 64, 3-stage cp.async,
//   256 threads / 8 warps (4x2), warp tile 32x64, 2 CTAs/SM.
// ---------------------------------------------------------------------------
#define NCH 8
#define KT_PER_CH 16       // 1024 / 64
#define NJOBS (NCH * KT_PER_CH)   // 128
#define A_STAGE 16384
#define STAGE 32768
#define VDP_OFF 98304
#define SROW_OFF 106496
#define RIDX_OFF 107008
#define SMEM_TOTAL 107520

__device__ __forceinline__ void load_job(uint32_t sb, const int* __restrict__ ridx,
                                         int slot, int j, int bT) {
    const int c = j >> 4, kt = j & 15;
    const int ksrc = kt << 6;
    const uint32_t aB = sb + slot * STAGE;
    const uint32_t bB = aB + A_STAGE;
    const int tid = threadIdx.x;
    const int n0 = c << 7;
#pragma unroll
    for (int i = 0; i < 4; i++) {         // A: 128 gathered rows x 128B
        int ch = i * 256 + tid;
        int row = ch >> 3, cu = ch & 7;
        uint32_t dst = aB + row * 128 + ((cu ^ (row & 7)) << 4);
        CP_ASYNC_16(dst, g_enc_h + (size_t)(bT + ridx[row]) * H + ksrc + cu * 8);
    }
#pragma unroll
    for (int i = 0; i < 4; i++) {         // B: 128 rows x 128B
        int ch = i * 256 + tid;
        int row = ch >> 3, cu = ch & 7;
        uint32_t dst = bB + row * 128 + ((cu ^ (row & 7)) << 4);
        CP_ASYNC_16(dst, g_W_h + (size_t)(n0 + row) * H + ksrc + cu * 8);
    }
}

__global__ __launch_bounds__(256, 2) void scores_tc_kernel(const float* __restrict__ v_g) {
    extern __shared__ char sm[];
    const uint32_t sb = smem_u32(sm);
    const int tid = threadIdx.x;
    const int b = blockIdx.x >> 4;
    const int m0 = (blockIdx.x & 15) * 128;
    const int cnt = g_cnt[b];
    if (m0 >= cnt) return;
    const int wid = tid >> 5, lane = tid & 31;
    const int wm = wid >> 1, wn = wid & 1;
    const int bT = b * T;

    float2* vdp = (float2*)(sm + VDP_OFF);
    float* srow = (float*)(sm + SROW_OFF);
    int* ridx = (int*)(sm + RIDX_OFF);
    for (int n = tid; n < H; n += 256) {
        float2 t;
        t.x = g_dec_p[b * H + n];
        t.y = v_g[n];
        vdp[n] = t;
    }
    if (tid < 128) {
        srow[tid] = 0.f;
        int j = m0 + tid;
        ridx[tid] = g_cidx[bT + (j < cnt ? j : cnt - 1)];
    }

    // ldmatrix per-lane geometry (warp tile 32M x 64N)
    int rA128[2], rAx[2], rB128[4], rBx[4];
#pragma unroll
    for (int mt = 0; mt < 2; mt++) {
        int row = wm * 32 + mt * 16 + ((lane >> 3) & 1) * 8 + (lane & 7);
        rA128[mt] = row * 128;
        rAx[mt] = row & 7;
    }
#pragma unroll
    for (int np = 0; np < 4; np++) {
        int row = wn * 64 + np * 16 + ((lane >> 4) << 3) + (lane & 7);
        rB128[np] = row * 128;
        rBx[np] = row & 7;
    }
    const int aU = lane >> 4;
    const int bU = (lane >> 3) & 1;

    __syncthreads();

    load_job(sb, ridx, 0, 0, bT); CP_COMMIT();
    load_job(sb, ridx, 1, 1, bT); CP_COMMIT();

    float c[2][8][4];
    float accA[2] = {0.f, 0.f};
    float accB[2] = {0.f, 0.f};
    int cch = 0, kt = 0;
    int slot = 0, slot2 = 2;

#pragma unroll 1
    for (int j = 0; j < NJOBS; j++) {
        CP_WAIT1();
        __syncthreads();
        {
            const int jn = j + 2;
            if (jn < NJOBS) load_job(sb, ridx, slot2, jn, bT);
            CP_COMMIT();
        }

        if (kt == 0) {
#pragma unroll
            for (int mt = 0; mt < 2; mt++)
#pragma unroll
                for (int nt = 0; nt < 8; nt++)
#pragma unroll
                    for (int q = 0; q < 4; q++) c[mt][nt][q] = 0.f;
        }

        const uint32_t aBase = sb + slot * STAGE;
        const uint32_t bBase = aBase + A_STAGE;

#pragma unroll
        for (int ks = 0; ks < 4; ks++) {
            uint32_t a[2][4];
#pragma unroll
            for (int mt = 0; mt < 2; mt++) {
                uint32_t ad = aBase + rA128[mt] + ((((ks << 1) + aU) ^ rAx[mt]) << 4);
                LDSM_X4(a[mt][0], a[mt][1], a[mt][2], a[mt][3], ad);
            }
            uint32_t bb[4][4];
#pragma unroll
            for (int np = 0; np < 4; np++) {
                uint32_t bd = bBase + rB128[np] + ((((ks << 1) + bU) ^ rBx[np]) << 4);
                LDSM_X4(bb[np][0], bb[np][1], bb[np][2], bb[np][3], bd);
            }
#pragma unroll
            for (int mt = 0; mt < 2; mt++)
#pragma unroll
                for (int np = 0; np < 4; np++) {
                    MMA16816(c[mt][2 * np][0], c[mt][2 * np][1], c[mt][2 * np][2], c[mt][2 * np][3],
                             a[mt][0], a[mt][1], a[mt][2], a[mt][3], bb[np][0], bb[np][1]);
                    MMA16816(c[mt][2 * np + 1][0], c[mt][2 * np + 1][1], c[mt][2 * np + 1][2], c[mt][2 * np + 1][3],
                             a[mt][0], a[mt][1], a[mt][2], a[mt][3], bb[np][2], bb[np][3]);
                }
        }

        if (kt == KT_PER_CH - 1) {
            const int nb = cch * 128 + wn * 64 + (lane & 3) * 2;
            const float inv32 = 0.03125f;
#pragma unroll
            for (int mt = 0; mt < 2; mt++)
#pragma unroll
                for (int nt = 0; nt < 8; nt++) {
                    int n = nb + nt * 8;
                    float2 d0 = vdp[n], d1 = vdp[n + 1];
                    accA[mt] += d0.y * fast_tanh(fmaf(c[mt][nt][0], inv32, d0.x))
                              + d1.y * fast_tanh(fmaf(c[mt][nt][1], inv32, d1.x));
                    accB[mt] += d0.y * fast_tanh(fmaf(c[mt][nt][2], inv32, d0.x))
                              + d1.y * fast_tanh(fmaf(c[mt][nt][3], inv32, d1.x));
                }
            cch++;
            kt = 0;
        } else {
            kt++;
        }
        slot = (slot == 2) ? 0 : slot + 1;
        slot2 = (slot2 == 2) ? 0 : slot2 + 1;
    }

    // reduce across the 4 n-lanes of each quad, then across warps via smem
#pragma unroll
    for (int mt = 0; mt < 2; mt++) {
        accA[mt] += __shfl_xor_sync(0xffffffffu, accA[mt], 1);
        accA[mt] += __shfl_xor_sync(0xffffffffu, accA[mt], 2);
        accB[mt] += __shfl_xor_sync(0xffffffffu, accB[mt], 1);
        accB[mt] += __shfl_xor_sync(0xffffffffu, accB[mt], 2);
        if ((lane & 3) == 0) {
            int r = wm * 32 + mt * 16 + (lane >> 2);
            atomicAdd(&srow[r], accA[mt]);
            atomicAdd(&srow[r + 8], accB[mt]);
        }
    }
    __syncthreads();
    if (tid < 128 && m0 + tid < cnt) g_scores[bT + ridx[tid]] = srow[tid];
}

// ---------------------------------------------------------------------------
// masked softmax over T, one block per batch row
// ---------------------------------------------------------------------------
__global__ void softmax_kernel(const int* __restrict__ mask,
                               float* __restrict__ attn) {
    const int b = blockIdx.x;
    const int tid = threadIdx.x;
    __shared__ float red[8];

    float vals[8];
    float mx = -INFINITY;
#pragma unroll
    for (int i = 0; i < 8; i++) {
        int t = tid + i * 256;
        float sc = (mask[b * T + t] == 0) ? NEGV : g_scores[b * T + t];
        vals[i] = sc;
        mx = fmaxf(mx, sc);
    }
#pragma unroll
    for (int off = 16; off; off >>= 1)
        mx = fmaxf(mx, __shfl_xor_sync(0xffffffffu, mx, off));
    if ((tid & 31) == 0) red[tid >> 5] = mx;
    __syncthreads();
    if (tid < 32) {
        float m = (tid < 8) ? red[tid] : -INFINITY;
#pragma unroll
        for (int off = 4; off; off >>= 1)
            m = fmaxf(m, __shfl_xor_sync(0xffffffffu, m, off));
        if (tid == 0) red[0] = m;
    }
    __syncthreads();
    mx = red[0];

    float sum = 0.f;
#pragma unroll
    for (int i = 0; i < 8; i++) {
        vals[i] = expf(vals[i] - mx);
        sum += vals[i];
    }
#pragma unroll
    for (int off = 16; off; off >>= 1)
        sum += __shfl_xor_sync(0xffffffffu, sum, off);
    __syncthreads();
    if ((tid & 31) == 0) red[tid >> 5] = sum;
    __syncthreads();
    if (tid < 32) {
        float s = (tid < 8) ? red[tid] : 0.f;
#pragma unroll
        for (int off = 4; off; off >>= 1)
            s += __shfl_xor_sync(0xffffffffu, s, off);
        if (tid == 0) red[0] = s;
    }
    __syncthreads();
    const float inv = 1.f / red[0];
#pragma unroll
    for (int i = 0; i < 8; i++)
        attn[b * T + tid + i * 256] = vals[i] * inv;
}

// ---------------------------------------------------------------------------
// context[b,h] = sum over UNMASKED t of attn[b,t]*enc_h[b,t,h]  (fp16 enc)
// ---------------------------------------------------------------------------
#define TSPLIT 8
__global__ void context_kernel(const float* __restrict__ attn,
                               float* __restrict__ ctx) {
    __shared__ float w[256];
    __shared__ int ti[256];
    const int b = blockIdx.y;
    const int cnt = g_cnt[b];
    const int chunk = (cnt + TSPLIT - 1) / TSPLIT;
    const int j0 = blockIdx.z * chunk;
    const int len = min(chunk, cnt - j0);
    const int tid = threadIdx.x;
    for (int j = tid; j < len; j += 256) {
        int t = g_cidx[b * T + j0 + j];
        ti[j] = t;
        w[j] = attn[b * T + t];
    }
    __syncthreads();
    if (len <= 0) return;

    const int h = blockIdx.x * 512 + tid * 2;
    const __half* e = g_enc_h + (size_t)b * T * H + h;
    float a0 = 0.f, a1 = 0.f;
#pragma unroll 4
    for (int j = 0; j < len; j++) {
        __half2 v2 = *(const __half2*)(e + (size_t)ti[j] * H);
        float2 f2 = __half22float2(v2);
        a0 = fmaf(w[j], f2.x, a0);
        a1 = fmaf(w[j], f2.y, a1);
    }
    atomicAdd(&ctx[b * H + h], a0);
    atomicAdd(&ctx[b * H + h + 1], a1);
}

// ---------------------------------------------------------------------------
extern "C" void kernel_launch(void* const* d_in, const int* in_sizes, int n_in,
                              void* d_out, int out_size) {
    const float* dec  = (const float*)d_in[0];  // [B,H]
    const float* enc  = (const float*)d_in[1];  // [B,T,H]
    const int*   mask = (const int*)d_in[2];    // [B,T]
    const float* We   = (const float*)d_in[3];  // [H,H]
    const float* Wd   = (const float*)d_in[4];  // [H,H]
    const float* v    = (const float*)d_in[5];  // [H]

    float* ctx  = (float*)d_out;                // [B,H]
    float* attn = (float*)d_out + B * H;        // [B,T]

    cudaFuncSetAttribute(scores_tc_kernel,
                         cudaFuncAttributeMaxDynamicSharedMemorySize, SMEM_TOTAL);

    compact_kernel<<<B, 256>>>(mask);
    conv_enc_kernel<<<(B * T * H / 4 + 255) / 256, 256>>>(enc, mask);
    conv_W_kernel<<<(H * H / 4 + 255) / 256, 256>>>(We);
    dec_proj_kernel<<<dim3(H / 32, 8), 256>>>(dec, Wd);
    cudaMemsetAsync(ctx, 0, (size_t)B * H * sizeof(float));

    scores_tc_kernel<<<B * 16, 256, SMEM_TOTAL>>>(v);

    softmax_kernel<<<B, 256>>>(mask, attn);
    context_kernel<<<dim3(H / 512, B, TSPLIT), 256>>>(attn, ctx);
}

// round 16
// speedup vs baseline: 1.1942x; 1.0009x over previous
#include <cuda_runtime.h>
#include <cuda_fp16.h>
#include <cstdint>
#include <math.h>

#define B 32
#define T 2048
#define H 1024
#define NEGV (-1e9f)

// ---------------------------------------------------------------------------
// Device scratch
// ---------------------------------------------------------------------------
__device__ __align__(256) __half g_enc_h[B * T * H];   // fp16(enc), unmasked rows only
__device__ __align__(256) __half g_W_h[H * H];         // fp16(32*W_enc)
__device__ float g_dec_p[B * H];
__device__ float g_scores[B * T];
__device__ int   g_cidx[B * T];                        // compacted t-indices per batch
__device__ int   g_cnt[B];

// ---------------------------------------------------------------------------
// helpers
// ---------------------------------------------------------------------------
__device__ __forceinline__ uint32_t smem_u32(const void* p) {
    uint32_t a;
    asm("{ .reg .u64 t; cvta.to.shared.u64 t, %1; cvt.u32.u64 %0, t; }" : "=r"(a) : "l"(p));
    return a;
}
#define CP_ASYNC_16(dst, src) \
    asm volatile("cp.async.cg.shared.global [%0], [%1], 16;" :: "r"(dst), "l"(src) : "memory")
#define CP_COMMIT() asm volatile("cp.async.commit_group;" ::: "memory")
#define CP_WAIT1()  asm volatile("cp.async.wait_group 1;" ::: "memory")

#define LDSM_X4(r0, r1, r2, r3, addr) \
    asm volatile("ldmatrix.sync.aligned.m8n8.x4.shared.b16 {%0,%1,%2,%3}, [%4];" \
        : "=r"(r0), "=r"(r1), "=r"(r2), "=r"(r3) : "r"(addr))

#define MMA16816(c0, c1, c2, c3, a0, a1, a2, a3, b0, b1) \
    asm volatile("mma.sync.aligned.m16n8k16.row.col.f32.f16.f16.f32 " \
        "{%0,%1,%2,%3}, {%4,%5,%6,%7}, {%8,%9}, {%0,%1,%2,%3};" \
        : "+f"(c0), "+f"(c1), "+f"(c2), "+f"(c3) \
        : "r"(a0), "r"(a1), "r"(a2), "r"(a3), "r"(b0), "r"(b1))

// single-MUFU tanh (sm_75+), rel err ~2^-11
__device__ __forceinline__ float fast_tanh(float x) {
    float r;
    asm("tanh.approx.f32 %0, %1;" : "=f"(r) : "f"(x));
    return r;
}

// ---------------------------------------------------------------------------
// Compaction + per-replay zeroing (dec_p, ctx)
// ---------------------------------------------------------------------------
__global__ void compact_kernel(const int* __restrict__ mask,
                               float* __restrict__ ctx) {
    __shared__ int warp_cnt[8];
    __shared__ int base;
    const int b = blockIdx.x;
    const int tid = threadIdx.x;
    const int lane = tid & 31, w = tid >> 5;
#pragma unroll
    for (int i = 0; i < 4; i++) {
        g_dec_p[b * H + i * 256 + tid] = 0.f;
        ctx[b * H + i * 256 + tid] = 0.f;
    }
    if (tid == 0) base = 0;
    __syncthreads();
    for (int t0 = 0; t0 < T; t0 += 256) {
        const int cur = base;
        const int t = t0 + tid;
        const int m = (mask[b * T + t] != 0);
        unsigned bal = __ballot_sync(0xffffffffu, m);
        int pre = __popc(bal & ((1u << lane) - 1u));
        if (lane == 0) warp_cnt[w] = __popc(bal);
        __syncthreads();
        int woff = 0, tot = 0;
#pragma unroll
        for (int i = 0; i < 8; i++) {
            if (i < w) woff += warp_cnt[i];
            tot += warp_cnt[i];
        }
        if (m) g_cidx[b * T + cur + woff + pre] = t;
        __syncthreads();
        if (tid == 0) base = cur + tot;
        __syncthreads();
    }
    if (tid == 0) g_cnt[b] = base;
}

// ---------------------------------------------------------------------------
// Mega prep kernel: dec_proj (256 blocks) + conv_W (1024) + conv_enc (65536).
// dec_proj/conv_W get low block indices -> scheduled first, overlap with the
// DRAM-bound conv_enc stream.
// ---------------------------------------------------------------------------
#define DP_BLOCKS 256
#define CW_BLOCKS 1024                       // H*H/4/256
#define CE_BLOCKS 65536                      // B*T*H/4/256
#define PREP_BLOCKS (DP_BLOCKS + CW_BLOCKS + CE_BLOCKS)

__global__ __launch_bounds__(256) void prep_kernel(const float* __restrict__ enc,
                                                   const int* __restrict__ mask,
                                                   const float* __restrict__ We,
                                                   const float* __restrict__ dec,
                                                   const float* __restrict__ Wd) {
    const int bid = blockIdx.x;
    const int tid = threadIdx.x;

    if (bid < DP_BLOCKS) {
        // ---- dec_proj split-K mini-GEMM: 32 o-tiles x 8 k-chunks ----
        __shared__ float sd[32][132];
        __shared__ float sw[32][132];
        const int o0 = (bid & 31) * 32;
        const int h0 = (bid >> 5) * 128;
        const int tx = tid & 15, ty = tid >> 4;
        float c00 = 0.f, c01 = 0.f, c10 = 0.f, c11 = 0.f;
#pragma unroll
        for (int i = 0; i < 4; i++) {
            int idx = i * 256 + tid;
            int row = idx >> 5;
            int col = (idx & 31) * 4;
            float4 xv = *(const float4*)(dec + (size_t)row * H + h0 + col);
            sd[row][col + 0] = xv.x; sd[row][col + 1] = xv.y;
            sd[row][col + 2] = xv.z; sd[row][col + 3] = xv.w;
            float4 wv = *(const float4*)(Wd + (size_t)(o0 + row) * H + h0 + col);
            sw[row][col + 0] = wv.x; sw[row][col + 1] = wv.y;
            sw[row][col + 2] = wv.z; sw[row][col + 3] = wv.w;
        }
        __syncthreads();
#pragma unroll 8
        for (int h = 0; h < 128; h++) {
            float a0 = sd[ty * 2][h], a1 = sd[ty * 2 + 1][h];
            float w0 = sw[tx * 2][h], w1 = sw[tx * 2 + 1][h];
            c00 = fmaf(a0, w0, c00); c01 = fmaf(a0, w1, c01);
            c10 = fmaf(a1, w0, c10); c11 = fmaf(a1, w1, c11);
        }
        const int b0 = ty * 2, oo = o0 + tx * 2;
        atomicAdd(&g_dec_p[b0 * H + oo], c00);
        atomicAdd(&g_dec_p[b0 * H + oo + 1], c01);
        atomicAdd(&g_dec_p[(b0 + 1) * H + oo], c10);
        atomicAdd(&g_dec_p[(b0 + 1) * H + oo + 1], c11);
    } else if (bid < DP_BLOCKS + CW_BLOCKS) {
        // ---- conv_W: fp32 We -> fp16 32*We ----
        int i = ((bid - DP_BLOCKS) * 256 + tid) * 4;
        float4 x = *(const float4*)(We + i);
        __half2 p0, p1;
        p0.x = __float2half(x.x * 32.f); p0.y = __float2half(x.y * 32.f);
        p1.x = __float2half(x.z * 32.f); p1.y = __float2half(x.w * 32.f);
        *(__half2*)(g_W_h + i) = p0;
        *(__half2*)(g_W_h + i + 2) = p1;
    } else {
        // ---- conv_enc: fp32 enc -> fp16, unmasked rows only ----
        int i = ((bid - DP_BLOCKS - CW_BLOCKS) * 256 + tid) * 4;
        if (mask[i >> 10] == 0) return;
        float4 x = *(const float4*)(enc + i);
        __half2 p0, p1;
        p0.x = __float2half(x.x); p0.y = __float2half(x.y);
        p1.x = __float2half(x.z); p1.y = __float2half(x.w);
        *(__half2*)(g_enc_h + i) = p0;
        *(__half2*)(g_enc_h + i + 2) = p1;
    }
}

// ---------------------------------------------------------------------------
// Fused HMMA scores kernel on COMPACTED rows
//   Block tile 128(Mc) x 128(N-chunk), K = 1024, k-tile 64, 3-stage cp.async,
//   256 threads / 8 warps (4x2), warp tile 32x64, 2 CTAs/SM.
// ---------------------------------------------------------------------------
#define NCH 8
#define KT_PER_CH 16       // 1024 / 64
#define NJOBS (NCH * KT_PER_CH)   // 128
#define A_STAGE 16384
#define STAGE 32768
#define VDP_OFF 98304
#define SROW_OFF 106496
#define RIDX_OFF 107008
#define SMEM_TOTAL 107520

__device__ __forceinline__ void load_job(uint32_t sb, const int* __restrict__ ridx,
                                         int slot, int j, int bT) {
    const int c = j >> 4, kt = j & 15;
    const int ksrc = kt << 6;
    const uint32_t aB = sb + slot * STAGE;
    const uint32_t bB = aB + A_STAGE;
    const int tid = threadIdx.x;
    const int n0 = c << 7;
#pragma unroll
    for (int i = 0; i < 4; i++) {         // A: 128 gathered rows x 128B
        int ch = i * 256 + tid;
        int row = ch >> 3, cu = ch & 7;
        uint32_t dst = aB + row * 128 + ((cu ^ (row & 7)) << 4);
        CP_ASYNC_16(dst, g_enc_h + (size_t)(bT + ridx[row]) * H + ksrc + cu * 8);
    }
#pragma unroll
    for (int i = 0; i < 4; i++) {         // B: 128 rows x 128B
        int ch = i * 256 + tid;
        int row = ch >> 3, cu = ch & 7;
        uint32_t dst = bB + row * 128 + ((cu ^ (row & 7)) << 4);
        CP_ASYNC_16(dst, g_W_h + (size_t)(n0 + row) * H + ksrc + cu * 8);
    }
}

__global__ __launch_bounds__(256, 2) void scores_tc_kernel(const float* __restrict__ v_g) {
    extern __shared__ char sm[];
    const uint32_t sb = smem_u32(sm);
    const int tid = threadIdx.x;
    const int b = blockIdx.x >> 4;
    const int m0 = (blockIdx.x & 15) * 128;
    const int cnt = g_cnt[b];
    if (m0 >= cnt) return;
    const int wid = tid >> 5, lane = tid & 31;
    const int wm = wid >> 1, wn = wid & 1;
    const int bT = b * T;

    float2* vdp = (float2*)(sm + VDP_OFF);
    float* srow = (float*)(sm + SROW_OFF);
    int* ridx = (int*)(sm + RIDX_OFF);
    for (int n = tid; n < H; n += 256) {
        float2 t;
        t.x = g_dec_p[b * H + n];
        t.y = v_g[n];
        vdp[n] = t;
    }
    if (tid < 128) {
        srow[tid] = 0.f;
        int j = m0 + tid;
        ridx[tid] = g_cidx[bT + (j < cnt ? j : cnt - 1)];
    }

    // ldmatrix per-lane geometry (warp tile 32M x 64N)
    int rA128[2], rAx[2], rB128[4], rBx[4];
#pragma unroll
    for (int mt = 0; mt < 2; mt++) {
        int row = wm * 32 + mt * 16 + ((lane >> 3) & 1) * 8 + (lane & 7);
        rA128[mt] = row * 128;
        rAx[mt] = row & 7;
    }
#pragma unroll
    for (int np = 0; np < 4; np++) {
        int row = wn * 64 + np * 16 + ((lane >> 4) << 3) + (lane & 7);
        rB128[np] = row * 128;
        rBx[np] = row & 7;
    }
    const int aU = lane >> 4;
    const int bU = (lane >> 3) & 1;

    __syncthreads();

    load_job(sb, ridx, 0, 0, bT); CP_COMMIT();
    load_job(sb, ridx, 1, 1, bT); CP_COMMIT();

    float c[2][8][4];
    float accA[2] = {0.f, 0.f};
    float accB[2] = {0.f, 0.f};
    int cch = 0, kt = 0;
    int slot = 0, slot2 = 2;

#pragma unroll 1
    for (int j = 0; j < NJOBS; j++) {
        CP_WAIT1();
        __syncthreads();
        {
            const int jn = j + 2;
            if (jn < NJOBS) load_job(sb, ridx, slot2, jn, bT);
            CP_COMMIT();
        }

        if (kt == 0) {
#pragma unroll
            for (int mt = 0; mt < 2; mt++)
#pragma unroll
                for (int nt = 0; nt < 8; nt++)
#pragma unroll
                    for (int q = 0; q < 4; q++) c[mt][nt][q] = 0.f;
        }

        const uint32_t aBase = sb + slot * STAGE;
        const uint32_t bBase = aBase + A_STAGE;

#pragma unroll
        for (int ks = 0; ks < 4; ks++) {
            uint32_t a[2][4];
#pragma unroll
            for (int mt = 0; mt < 2; mt++) {
                uint32_t ad = aBase + rA128[mt] + ((((ks << 1) + aU) ^ rAx[mt]) << 4);
                LDSM_X4(a[mt][0], a[mt][1], a[mt][2], a[mt][3], ad);
            }
            uint32_t bb[4][4];
#pragma unroll
            for (int np = 0; np < 4; np++) {
                uint32_t bd = bBase + rB128[np] + ((((ks << 1) + bU) ^ rBx[np]) << 4);
                LDSM_X4(bb[np][0], bb[np][1], bb[np][2], bb[np][3], bd);
            }
#pragma unroll
            for (int mt = 0; mt < 2; mt++)
#pragma unroll
                for (int np = 0; np < 4; np++) {
                    MMA16816(c[mt][2 * np][0], c[mt][2 * np][1], c[mt][2 * np][2], c[mt][2 * np][3],
                             a[mt][0], a[mt][1], a[mt][2], a[mt][3], bb[np][0], bb[np][1]);
                    MMA16816(c[mt][2 * np + 1][0], c[mt][2 * np + 1][1], c[mt][2 * np + 1][2], c[mt][2 * np + 1][3],
                             a[mt][0], a[mt][1], a[mt][2], a[mt][3], bb[np][2], bb[np][3]);
                }
        }

        if (kt == KT_PER_CH - 1) {
            const int nb = cch * 128 + wn * 64 + (lane & 3) * 2;
            const float inv32 = 0.03125f;
#pragma unroll
            for (int mt = 0; mt < 2; mt++)
#pragma unroll
                for (int nt = 0; nt < 8; nt++) {
                    int n = nb + nt * 8;
                    float2 d0 = vdp[n], d1 = vdp[n + 1];
                    accA[mt] += d0.y * fast_tanh(fmaf(c[mt][nt][0], inv32, d0.x))
                              + d1.y * fast_tanh(fmaf(c[mt][nt][1], inv32, d1.x));
                    accB[mt] += d0.y * fast_tanh(fmaf(c[mt][nt][2], inv32, d0.x))
                              + d1.y * fast_tanh(fmaf(c[mt][nt][3], inv32, d1.x));
                }
            cch++;
            kt = 0;
        } else {
            kt++;
        }
        slot = (slot == 2) ? 0 : slot + 1;
        slot2 = (slot2 == 2) ? 0 : slot2 + 1;
    }

    // reduce across the 4 n-lanes of each quad, then across warps via smem
#pragma unroll
    for (int mt = 0; mt < 2; mt++) {
        accA[mt] += __shfl_xor_sync(0xffffffffu, accA[mt], 1);
        accA[mt] += __shfl_xor_sync(0xffffffffu, accA[mt], 2);
        accB[mt] += __shfl_xor_sync(0xffffffffu, accB[mt], 1);
        accB[mt] += __shfl_xor_sync(0xffffffffu, accB[mt], 2);
        if ((lane & 3) == 0) {
            int r = wm * 32 + mt * 16 + (lane >> 2);
            atomicAdd(&srow[r], accA[mt]);
            atomicAdd(&srow[r + 8], accB[mt]);
        }
    }
    __syncthreads();
    if (tid < 128 && m0 + tid < cnt) g_scores[bT + ridx[tid]] = srow[tid];
}

// ---------------------------------------------------------------------------
// masked softmax over T, one block per batch row
// ---------------------------------------------------------------------------
__global__ void softmax_kernel(const int* __restrict__ mask,
                               float* __restrict__ attn) {
    const int b = blockIdx.x;
    const int tid = threadIdx.x;
    __shared__ float red[8];

    float vals[8];
    float mx = -INFINITY;
#pragma unroll
    for (int i = 0; i < 8; i++) {
        int t = tid + i * 256;
        float sc = (mask[b * T + t] == 0) ? NEGV : g_scores[b * T + t];
        vals[i] = sc;
        mx = fmaxf(mx, sc);
    }
#pragma unroll
    for (int off = 16; off; off >>= 1)
        mx = fmaxf(mx, __shfl_xor_sync(0xffffffffu, mx, off));
    if ((tid & 31) == 0) red[tid >> 5] = mx;
    __syncthreads();
    if (tid < 32) {
        float m = (tid < 8) ? red[tid] : -INFINITY;
#pragma unroll
        for (int off = 4; off; off >>= 1)
            m = fmaxf(m, __shfl_xor_sync(0xffffffffu, m, off));
        if (tid == 0) red[0] = m;
    }
    __syncthreads();
    mx = red[0];

    float sum = 0.f;
#pragma unroll
    for (int i = 0; i < 8; i++) {
        vals[i] = expf(vals[i] - mx);
        sum += vals[i];
    }
#pragma unroll
    for (int off = 16; off; off >>= 1)
        sum += __shfl_xor_sync(0xffffffffu, sum, off);
    __syncthreads();
    if ((tid & 31) == 0) red[tid >> 5] = sum;
    __syncthreads();
    if (tid < 32) {
        float s = (tid < 8) ? red[tid] : 0.f;
#pragma unroll
        for (int off = 4; off; off >>= 1)
            s += __shfl_xor_sync(0xffffffffu, s, off);
        if (tid == 0) red[0] = s;
    }
    __syncthreads();
    const float inv = 1.f / red[0];
#pragma unroll
    for (int i = 0; i < 8; i++)
        attn[b * T + tid + i * 256] = vals[i] * inv;
}

// ---------------------------------------------------------------------------
// context[b,h] = sum over UNMASKED t of attn[b,t]*enc_h[b,t,h]  (fp16 enc)
// ---------------------------------------------------------------------------
#define TSPLIT 8
__global__ void context_kernel(const float* __restrict__ attn,
                               float* __restrict__ ctx) {
    __shared__ float w[256];
    __shared__ int ti[256];
    const int b = blockIdx.y;
    const int cnt = g_cnt[b];
    const int chunk = (cnt + TSPLIT - 1) / TSPLIT;
    const int j0 = blockIdx.z * chunk;
    const int len = min(chunk, cnt - j0);
    const int tid = threadIdx.x;
    for (int j = tid; j < len; j += 256) {
        int t = g_cidx[b * T + j0 + j];
        ti[j] = t;
        w[j] = attn[b * T + t];
    }
    __syncthreads();
    if (len <= 0) return;

    const int h = blockIdx.x * 512 + tid * 2;
    const __half* e = g_enc_h + (size_t)b * T * H + h;
    float a0 = 0.f, a1 = 0.f;
#pragma unroll 4
    for (int j = 0; j < len; j++) {
        __half2 v2 = *(const __half2*)(e + (size_t)ti[j] * H);
        float2 f2 = __half22float2(v2);
        a0 = fmaf(w[j], f2.x, a0);
        a1 = fmaf(w[j], f2.y, a1);
    }
    atomicAdd(&ctx[b * H + h], a0);
    atomicAdd(&ctx[b * H + h + 1], a1);
}

// ---------------------------------------------------------------------------
extern "C" void kernel_launch(void* const* d_in, const int* in_sizes, int n_in,
                              void* d_out, int out_size) {
    const float* dec  = (const float*)d_in[0];  // [B,H]
    const float* enc  = (const float*)d_in[1];  // [B,T,H]
    const int*   mask = (const int*)d_in[2];    // [B,T]
    const float* We   = (const float*)d_in[3];  // [H,H]
    const float* Wd   = (const float*)d_in[4];  // [H,H]
    const float* v    = (const float*)d_in[5];  // [H]

    float* ctx  = (float*)d_out;                // [B,H]
    float* attn = (float*)d_out + B * H;        // [B,T]

    cudaFuncSetAttribute(scores_tc_kernel,
                         cudaFuncAttributeMaxDynamicSharedMemorySize, SMEM_TOTAL);

    compact_kernel<<<B, 256>>>(mask, ctx);
    prep_kernel<<<PREP_BLOCKS, 256>>>(enc, mask, We, dec, Wd);

    scores_tc_kernel<<<B * 16, 256, SMEM_TOTAL>>>(v);

    softmax_kernel<<<B, 256>>>(mask, attn);
    context_kernel<<<dim3(H / 512, B, TSPLIT), 256>>>(attn, ctx);
}

// round 17
// speedup vs baseline: 1.2001x; 1.0050x over previous
#include <cuda_runtime.h>
#include <cuda_fp16.h>
#include <cstdint>
#include <math.h>

#define B 32
#define T 2048
#define H 1024
#define NEGV (-1e9f)

// ---------------------------------------------------------------------------
// Device scratch
// ---------------------------------------------------------------------------
__device__ __align__(256) __half g_enc_h[B * T * H];   // fp16(enc), unmasked rows only
__device__ __align__(256) __half g_W_h[H * H];         // fp16(32*W_enc)
__device__ float g_dec_p[B * H];
__device__ float g_scores[B * T];
__device__ int   g_cidx[B * T];                        // compacted t-indices per batch
__device__ int   g_cnt[B];

// ---------------------------------------------------------------------------
// helpers
// ---------------------------------------------------------------------------
__device__ __forceinline__ uint32_t smem_u32(const void* p) {
    uint32_t a;
    asm("{ .reg .u64 t; cvta.to.shared.u64 t, %1; cvt.u32.u64 %0, t; }" : "=r"(a) : "l"(p));
    return a;
}
#define CP_ASYNC_16(dst, src) \
    asm volatile("cp.async.cg.shared.global [%0], [%1], 16;" :: "r"(dst), "l"(src) : "memory")
#define CP_COMMIT() asm volatile("cp.async.commit_group;" ::: "memory")
#define CP_WAIT1()  asm volatile("cp.async.wait_group 1;" ::: "memory")

#define LDSM_X4(r0, r1, r2, r3, addr) \
    asm volatile("ldmatrix.sync.aligned.m8n8.x4.shared.b16 {%0,%1,%2,%3}, [%4];" \
        : "=r"(r0), "=r"(r1), "=r"(r2), "=r"(r3) : "r"(addr))

#define MMA16816(c0, c1, c2, c3, a0, a1, a2, a3, b0, b1) \
    asm volatile("mma.sync.aligned.m16n8k16.row.col.f32.f16.f16.f32 " \
        "{%0,%1,%2,%3}, {%4,%5,%6,%7}, {%8,%9}, {%0,%1,%2,%3};" \
        : "+f"(c0), "+f"(c1), "+f"(c2), "+f"(c3) \
        : "r"(a0), "r"(a1), "r"(a2), "r"(a3), "r"(b0), "r"(b1))

// single-MUFU tanh (sm_75+), rel err ~2^-11
__device__ __forceinline__ float fast_tanh(float x) {
    float r;
    asm("tanh.approx.f32 %0, %1;" : "=f"(r) : "f"(x));
    return r;
}

// ---------------------------------------------------------------------------
// Mega prep kernel:
//   blocks [0, 32)                 : compaction + dec_p/ctx zeroing
//   blocks [32, 288)               : dec_proj split-K mini-GEMM
//   blocks [288, 1312)             : conv_W
//   blocks [1312, 1312 + 65536)    : conv_enc (unmasked rows)
// ---------------------------------------------------------------------------
#define CMP_BLOCKS 32
#define DP_BLOCKS 256
#define CW_BLOCKS 1024                       // H*H/4/256
#define CE_BLOCKS 65536                      // B*T*H/4/256
#define PREP_BLOCKS (CMP_BLOCKS + DP_BLOCKS + CW_BLOCKS + CE_BLOCKS)

__global__ __launch_bounds__(256) void prep_kernel(const float* __restrict__ enc,
                                                   const int* __restrict__ mask,
                                                   const float* __restrict__ We,
                                                   const float* __restrict__ dec,
                                                   const float* __restrict__ Wd,
                                                   float* __restrict__ ctx) {
    const int bid = blockIdx.x;
    const int tid = threadIdx.x;

    if (bid < CMP_BLOCKS) {
        // ---- compaction + per-replay zeroing ----
        __shared__ int warp_cnt[8];
        __shared__ int base;
        const int b = bid;
        const int lane = tid & 31, w = tid >> 5;
#pragma unroll
        for (int i = 0; i < 4; i++) {
            g_dec_p[b * H + i * 256 + tid] = 0.f;
            ctx[b * H + i * 256 + tid] = 0.f;
        }
        if (tid == 0) base = 0;
        __syncthreads();
        for (int t0 = 0; t0 < T; t0 += 256) {
            const int cur = base;
            const int t = t0 + tid;
            const int m = (mask[b * T + t] != 0);
            unsigned bal = __ballot_sync(0xffffffffu, m);
            int pre = __popc(bal & ((1u << lane) - 1u));
            if (lane == 0) warp_cnt[w] = __popc(bal);
            __syncthreads();
            int woff = 0, tot = 0;
#pragma unroll
            for (int i = 0; i < 8; i++) {
                if (i < w) woff += warp_cnt[i];
                tot += warp_cnt[i];
            }
            if (m) g_cidx[b * T + cur + woff + pre] = t;
            __syncthreads();
            if (tid == 0) base = cur + tot;
            __syncthreads();
        }
        if (tid == 0) g_cnt[b] = base;
    } else if (bid < CMP_BLOCKS + DP_BLOCKS) {
        // ---- dec_proj split-K mini-GEMM: 32 o-tiles x 8 k-chunks ----
        __shared__ float sd[32][132];
        __shared__ float sw[32][132];
        const int db = bid - CMP_BLOCKS;
        const int o0 = (db & 31) * 32;
        const int h0 = (db >> 5) * 128;
        const int tx = tid & 15, ty = tid >> 4;
        float c00 = 0.f, c01 = 0.f, c10 = 0.f, c11 = 0.f;
#pragma unroll
        for (int i = 0; i < 4; i++) {
            int idx = i * 256 + tid;
            int row = idx >> 5;
            int col = (idx & 31) * 4;
            float4 xv = *(const float4*)(dec + (size_t)row * H + h0 + col);
            sd[row][col + 0] = xv.x; sd[row][col + 1] = xv.y;
            sd[row][col + 2] = xv.z; sd[row][col + 3] = xv.w;
            float4 wv = *(const float4*)(Wd + (size_t)(o0 + row) * H + h0 + col);
            sw[row][col + 0] = wv.x; sw[row][col + 1] = wv.y;
            sw[row][col + 2] = wv.z; sw[row][col + 3] = wv.w;
        }
        __syncthreads();
#pragma unroll 8
        for (int h = 0; h < 128; h++) {
            float a0 = sd[ty * 2][h], a1 = sd[ty * 2 + 1][h];
            float w0 = sw[tx * 2][h], w1 = sw[tx * 2 + 1][h];
            c00 = fmaf(a0, w0, c00); c01 = fmaf(a0, w1, c01);
            c10 = fmaf(a1, w0, c10); c11 = fmaf(a1, w1, c11);
        }
        const int b0 = ty * 2, oo = o0 + tx * 2;
        atomicAdd(&g_dec_p[b0 * H + oo], c00);
        atomicAdd(&g_dec_p[b0 * H + oo + 1], c01);
        atomicAdd(&g_dec_p[(b0 + 1) * H + oo], c10);
        atomicAdd(&g_dec_p[(b0 + 1) * H + oo + 1], c11);
    } else if (bid < CMP_BLOCKS + DP_BLOCKS + CW_BLOCKS) {
        // ---- conv_W: fp32 We -> fp16 32*We ----
        int i = ((bid - CMP_BLOCKS - DP_BLOCKS) * 256 + tid) * 4;
        float4 x = *(const float4*)(We + i);
        __half2 p0, p1;
        p0.x = __float2half(x.x * 32.f); p0.y = __float2half(x.y * 32.f);
        p1.x = __float2half(x.z * 32.f); p1.y = __float2half(x.w * 32.f);
        *(__half2*)(g_W_h + i) = p0;
        *(__half2*)(g_W_h + i + 2) = p1;
    } else {
        // ---- conv_enc: fp32 enc -> fp16, unmasked rows only ----
        int i = ((bid - CMP_BLOCKS - DP_BLOCKS - CW_BLOCKS) * 256 + tid) * 4;
        if (mask[i >> 10] == 0) return;
        float4 x = *(const float4*)(enc + i);
        __half2 p0, p1;
        p0.x = __float2half(x.x); p0.y = __float2half(x.y);
        p1.x = __float2half(x.z); p1.y = __float2half(x.w);
        *(__half2*)(g_enc_h + i) = p0;
        *(__half2*)(g_enc_h + i + 2) = p1;
    }
}

// ---------------------------------------------------------------------------
// Fused HMMA scores kernel on COMPACTED rows
//   Block tile 128(Mc) x 128(N-chunk), K = 1024, k-tile 64, 3-stage cp.async,
//   256 threads / 8 warps (4x2), warp tile 32x64, 2 CTAs/SM.
// ---------------------------------------------------------------------------
#define NCH 8
#define KT_PER_CH 16       // 1024 / 64
#define NJOBS (NCH * KT_PER_CH)   // 128
#define A_STAGE 16384
#define STAGE 32768
#define VDP_OFF 98304
#define SROW_OFF 106496
#define RIDX_OFF 107008
#define SMEM_TOTAL 107520

__device__ __forceinline__ void load_job(uint32_t sb, const int* __restrict__ ridx,
                                         int slot, int j, int bT) {
    const int c = j >> 4, kt = j & 15;
    const int ksrc = kt << 6;
    const uint32_t aB = sb + slot * STAGE;
    const uint32_t bB = aB + A_STAGE;
    const int tid = threadIdx.x;
    const int n0 = c << 7;
#pragma unroll
    for (int i = 0; i < 4; i++) {         // A: 128 gathered rows x 128B
        int ch = i * 256 + tid;
        int row = ch >> 3, cu = ch & 7;
        uint32_t dst = aB + row * 128 + ((cu ^ (row & 7)) << 4);
        CP_ASYNC_16(dst, g_enc_h + (size_t)(bT + ridx[row]) * H + ksrc + cu * 8);
    }
#pragma unroll
    for (int i = 0; i < 4; i++) {         // B: 128 rows x 128B
        int ch = i * 256 + tid;
        int row = ch >> 3, cu = ch & 7;
        uint32_t dst = bB + row * 128 + ((cu ^ (row & 7)) << 4);
        CP_ASYNC_16(dst, g_W_h + (size_t)(n0 + row) * H + ksrc + cu * 8);
    }
}

__global__ __launch_bounds__(256, 2) void scores_tc_kernel(const float* __restrict__ v_g) {
    extern __shared__ char sm[];
    const uint32_t sb = smem_u32(sm);
    const int tid = threadIdx.x;
    const int b = blockIdx.x >> 4;
    const int m0 = (blockIdx.x & 15) * 128;
    const int cnt = g_cnt[b];
    if (m0 >= cnt) return;
    const int wid = tid >> 5, lane = tid & 31;
    const int wm = wid >> 1, wn = wid & 1;
    const int bT = b * T;

    float2* vdp = (float2*)(sm + VDP_OFF);
    float* srow = (float*)(sm + SROW_OFF);
    int* ridx = (int*)(sm + RIDX_OFF);
    for (int n = tid; n < H; n += 256) {
        float2 t;
        t.x = g_dec_p[b * H + n];
        t.y = v_g[n];
        vdp[n] = t;
    }
    if (tid < 128) {
        srow[tid] = 0.f;
        int j = m0 + tid;
        ridx[tid] = g_cidx[bT + (j < cnt ? j : cnt - 1)];
    }

    // ldmatrix per-lane geometry (warp tile 32M x 64N)
    int rA128[2], rAx[2], rB128[4], rBx[4];
#pragma unroll
    for (int mt = 0; mt < 2; mt++) {
        int row = wm * 32 + mt * 16 + ((lane >> 3) & 1) * 8 + (lane & 7);
        rA128[mt] = row * 128;
        rAx[mt] = row & 7;
    }
#pragma unroll
    for (int np = 0; np < 4; np++) {
        int row = wn * 64 + np * 16 + ((lane >> 4) << 3) + (lane & 7);
        rB128[np] = row * 128;
        rBx[np] = row & 7;
    }
    const int aU = lane >> 4;
    const int bU = (lane >> 3) & 1;

    __syncthreads();

    load_job(sb, ridx, 0, 0, bT); CP_COMMIT();
    load_job(sb, ridx, 1, 1, bT); CP_COMMIT();

    float c[2][8][4];
    float accA[2] = {0.f, 0.f};
    float accB[2] = {0.f, 0.f};
    int cch = 0, kt = 0;
    int slot = 0, slot2 = 2;

#pragma unroll 1
    for (int j = 0; j < NJOBS; j++) {
        CP_WAIT1();
        __syncthreads();
        {
            const int jn = j + 2;
            if (jn < NJOBS) load_job(sb, ridx, slot2, jn, bT);
            CP_COMMIT();
        }

        if (kt == 0) {
#pragma unroll
            for (int mt = 0; mt < 2; mt++)
#pragma unroll
                for (int nt = 0; nt < 8; nt++)
#pragma unroll
                    for (int q = 0; q < 4; q++) c[mt][nt][q] = 0.f;
        }

        const uint32_t aBase = sb + slot * STAGE;
        const uint32_t bBase = aBase + A_STAGE;

#pragma unroll
        for (int ks = 0; ks < 4; ks++) {
            uint32_t a[2][4];
#pragma unroll
            for (int mt = 0; mt < 2; mt++) {
                uint32_t ad = aBase + rA128[mt] + ((((ks << 1) + aU) ^ rAx[mt]) << 4);
                LDSM_X4(a[mt][0], a[mt][1], a[mt][2], a[mt][3], ad);
            }
            uint32_t bb[4][4];
#pragma unroll
            for (int np = 0; np < 4; np++) {
                uint32_t bd = bBase + rB128[np] + ((((ks << 1) + bU) ^ rBx[np]) << 4);
                LDSM_X4(bb[np][0], bb[np][1], bb[np][2], bb[np][3], bd);
            }
#pragma unroll
            for (int mt = 0; mt < 2; mt++)
#pragma unroll
                for (int np = 0; np < 4; np++) {
                    MMA16816(c[mt][2 * np][0], c[mt][2 * np][1], c[mt][2 * np][2], c[mt][2 * np][3],
                             a[mt][0], a[mt][1], a[mt][2], a[mt][3], bb[np][0], bb[np][1]);
                    MMA16816(c[mt][2 * np + 1][0], c[mt][2 * np + 1][1], c[mt][2 * np + 1][2], c[mt][2 * np + 1][3],
                             a[mt][0], a[mt][1], a[mt][2], a[mt][3], bb[np][2], bb[np][3]);
                }
        }

        if (kt == KT_PER_CH - 1) {
            const int nb = cch * 128 + wn * 64 + (lane & 3) * 2;
            const float inv32 = 0.03125f;
#pragma unroll
            for (int mt = 0; mt < 2; mt++)
#pragma unroll
                for (int nt = 0; nt < 8; nt++) {
                    int n = nb + nt * 8;
                    float2 d0 = vdp[n], d1 = vdp[n + 1];
                    accA[mt] += d0.y * fast_tanh(fmaf(c[mt][nt][0], inv32, d0.x))
                              + d1.y * fast_tanh(fmaf(c[mt][nt][1], inv32, d1.x));
                    accB[mt] += d0.y * fast_tanh(fmaf(c[mt][nt][2], inv32, d0.x))
                              + d1.y * fast_tanh(fmaf(c[mt][nt][3], inv32, d1.x));
                }
            cch++;
            kt = 0;
        } else {
            kt++;
        }
        slot = (slot == 2) ? 0 : slot + 1;
        slot2 = (slot2 == 2) ? 0 : slot2 + 1;
    }

    // reduce across the 4 n-lanes of each quad, then across warps via smem
#pragma unroll
    for (int mt = 0; mt < 2; mt++) {
        accA[mt] += __shfl_xor_sync(0xffffffffu, accA[mt], 1);
        accA[mt] += __shfl_xor_sync(0xffffffffu, accA[mt], 2);
        accB[mt] += __shfl_xor_sync(0xffffffffu, accB[mt], 1);
        accB[mt] += __shfl_xor_sync(0xffffffffu, accB[mt], 2);
        if ((lane & 3) == 0) {
            int r = wm * 32 + mt * 16 + (lane >> 2);
            atomicAdd(&srow[r], accA[mt]);
            atomicAdd(&srow[r + 8], accB[mt]);
        }
    }
    __syncthreads();
    if (tid < 128 && m0 + tid < cnt) g_scores[bT + ridx[tid]] = srow[tid];
}

// ---------------------------------------------------------------------------
// Fused softmax + context kernel.
//   Each block recomputes its batch's softmax stats (max, sum) from g_scores
//   (cheap, L2-hot), derives chunk weights directly, and accumulates
//   ctx[b,h] over its t-chunk. Block (x==0, z==0) also writes attn[b,:].
// ---------------------------------------------------------------------------
#define TSPLIT 8
__global__ void context_kernel(const int* __restrict__ mask,
                               float* __restrict__ attn,
                               float* __restrict__ ctx) {
    __shared__ float red[8];
    __shared__ float w[256];
    __shared__ int ti[256];
    const int b = blockIdx.y;
    const int bT = b * T;
    const int tid = threadIdx.x;

    // ---- softmax stats over all T (redundant per block) ----
    float vals[8];
    float mx = -INFINITY;
#pragma unroll
    for (int i = 0; i < 8; i++) {
        int t = tid + i * 256;
        float sc = (mask[bT + t] == 0) ? NEGV : g_scores[bT + t];
        vals[i] = sc;
        mx = fmaxf(mx, sc);
    }
#pragma unroll
    for (int off = 16; off; off >>= 1)
        mx = fmaxf(mx, __shfl_xor_sync(0xffffffffu, mx, off));
    if ((tid & 31) == 0) red[tid >> 5] = mx;
    __syncthreads();
    if (tid < 32) {
        float m = (tid < 8) ? red[tid] : -INFINITY;
#pragma unroll
        for (int off = 4; off; off >>= 1)
            m = fmaxf(m, __shfl_xor_sync(0xffffffffu, m, off));
        if (tid == 0) red[0] = m;
    }
    __syncthreads();
    mx = red[0];

    float sum = 0.f;
#pragma unroll
    for (int i = 0; i < 8; i++) {
        vals[i] = expf(vals[i] - mx);
        sum += vals[i];
    }
#pragma unroll
    for (int off = 16; off; off >>= 1)
        sum += __shfl_xor_sync(0xffffffffu, sum, off);
    __syncthreads();
    if ((tid & 31) == 0) red[tid >> 5] = sum;
    __syncthreads();
    if (tid < 32) {
        float s = (tid < 8) ? red[tid] : 0.f;
#pragma unroll
        for (int off = 4; off; off >>= 1)
            s += __shfl_xor_sync(0xffffffffu, s, off);
        if (tid == 0) red[0] = s;
    }
    __syncthreads();
    const float inv = 1.f / red[0];

    // designated block writes attn output for this batch
    if (blockIdx.x == 0 && blockIdx.z == 0) {
#pragma unroll
        for (int i = 0; i < 8; i++)
            attn[bT + tid + i * 256] = vals[i] * inv;
    }

    // ---- chunk weights + fp16 context accumulate ----
    const int cnt = g_cnt[b];
    const int chunk = (cnt + TSPLIT - 1) / TSPLIT;
    const int j0 = blockIdx.z * chunk;
    const int len = min(chunk, cnt - j0);
    __syncthreads();   // red/vals done before reusing smem
    for (int j = tid; j < len; j += 256) {
        int t = g_cidx[bT + j0 + j];
        ti[j] = t;
        w[j] = expf(g_scores[bT + t] - mx) * inv;
    }
    __syncthreads();
    if (len <= 0) return;

    const int h = blockIdx.x * 512 + tid * 2;
    const __half* e = g_enc_h + (size_t)bT * H + h;
    float a0 = 0.f, a1 = 0.f;
#pragma unroll 4
    for (int j = 0; j < len; j++) {
        __half2 v2 = *(const __half2*)(e + (size_t)ti[j] * H);
        float2 f2 = __half22float2(v2);
        a0 = fmaf(w[j], f2.x, a0);
        a1 = fmaf(w[j], f2.y, a1);
    }
    atomicAdd(&ctx[b * H + h], a0);
    atomicAdd(&ctx[b * H + h + 1], a1);
}

// ---------------------------------------------------------------------------
extern "C" void kernel_launch(void* const* d_in, const int* in_sizes, int n_in,
                              void* d_out, int out_size) {
    const float* dec  = (const float*)d_in[0];  // [B,H]
    const float* enc  = (const float*)d_in[1];  // [B,T,H]
    const int*   mask = (const int*)d_in[2];    // [B,T]
    const float* We   = (const float*)d_in[3];  // [H,H]
    const float* Wd   = (const float*)d_in[4];  // [H,H]
    const float* v    = (const float*)d_in[5];  // [H]

    float* ctx  = (float*)d_out;                // [B,H]
    float* attn = (float*)d_out + B * H;        // [B,T]

    cudaFuncSetAttribute(scores_tc_kernel,
                         cudaFuncAttributeMaxDynamicSharedMemorySize, SMEM_TOTAL);

    prep_kernel<<<PREP_BLOCKS, 256>>>(enc, mask, We, dec, Wd, ctx);

    scores_tc_kernel<<<B * 16, 256, SMEM_TOTAL>>>(v);

    context_kernel<<<dim3(H / 512, B, TSPLIT), 256>>>(mask, attn, ctx);
}